// round 9
// baseline (speedup 1.0000x reference)
#include <cuda_runtime.h>
#include <cuda_fp16.h>
#include <math.h>
#include <stdint.h>

#define NNODES 50000
#define NEDGES 800000
#define ETOT   (NEDGES + NNODES)
#define NLBL   100000
#define FIN    128
#define HH     4
#define CC     64
#define DD     256

// ---------------- scratch (device globals; no allocation allowed) ----------
__device__ int    g_flag64_e;
__device__ int    g_flag64_l;
__device__ int    g_rowptr[NNODES + 1];
__device__ int    g_fill[NNODES];
__device__ int    g_incl[NNODES];
__device__ int    g_bsum[256];
__device__ int    g_csr_src[ETOT];
__device__ int    g_esrc[ETOT];
__device__ int    g_edst[ETOT];
__device__ int    g_lu[NLBL];
__device__ int    g_lv[NLBL];
__device__ __half g_xh[(size_t)NNODES * FIN];   // x converted to fp16
__device__ __half g_hbuf[(size_t)NNODES * DD];  // GEMM output (fp16) / agg input
__device__ __half g_zh[(size_t)NNODES * DD];    // agg output (fp16) / GEMM input
__device__ float  g_als[NNODES * HH];
__device__ float  g_ald[NNODES * HH];
__device__ float  g_pr[(size_t)NNODES * 128];   // scorer P|R per node (fp32)
__device__ __half g_Wt1h[256 * 128];            // W1^T fp16
__device__ __half g_Wt2h[256 * 256];            // W2^T fp16
__device__ __half g_Wtsh[128 * 256];            // [Ws1_top|Ws1_bot]^T fp16

// ============================ helpers =======================================
__device__ __forceinline__ uint32_t pack_h2(float a, float b) {
    __half2 h = __floats2half2_rn(a, b);
    return *(uint32_t*)&h;
}

__device__ __forceinline__ void mma16816(float& c0, float& c1, float& c2, float& c3,
                                         uint32_t a0, uint32_t a1, uint32_t a2, uint32_t a3,
                                         uint32_t b0, uint32_t b1) {
    asm volatile(
        "mma.sync.aligned.m16n8k16.row.col.f32.f16.f16.f32 "
        "{%0,%1,%2,%3}, {%4,%5,%6,%7}, {%8,%9}, {%0,%1,%2,%3};"
        : "+f"(c0), "+f"(c1), "+f"(c2), "+f"(c3)
        : "r"(a0), "r"(a1), "r"(a2), "r"(a3), "r"(b0), "r"(b1));
}

// ---------------- init: zero hist + dtype detection --------------------------
__device__ __forceinline__ int check_is_i64(const long long* q) {
    int ok = 1;
#pragma unroll
    for (int i = 0; i < 8; i++) {
        long long v = q[i];
        if (v < 0 || v >= NNODES) ok = 0;
    }
    return ok;
}

__global__ void init_k(const void* ei, const void* eli) {
    int i = blockIdx.x * blockDim.x + threadIdx.x;
    if (i < NNODES) g_fill[i] = 0;
    if (i == 0) {
        g_flag64_e = check_is_i64((const long long*)ei);
        g_flag64_l = check_is_i64((const long long*)eli);
    }
}

// ---------------- edge conversion + self loops + histogram ------------------
__global__ void build_edges(const void* ei) {
    int i = blockIdx.x * blockDim.x + threadIdx.x;
    if (i >= ETOT) return;
    int s, d;
    if (i < NEDGES) {
        if (g_flag64_e) {
            const long long* q = (const long long*)ei;
            s = (int)q[i]; d = (int)q[NEDGES + i];
        } else {
            const int* q = (const int*)ei;
            s = q[i]; d = q[NEDGES + i];
        }
    } else {
        s = i - NEDGES; d = s;   // self loop
    }
    g_esrc[i] = s; g_edst[i] = d;
    atomicAdd(&g_fill[d], 1);
}

__global__ void build_labels(const void* eli) {
    int i = blockIdx.x * blockDim.x + threadIdx.x;
    if (i >= NLBL) return;
    if (g_flag64_l) {
        const long long* q = (const long long*)eli;
        g_lu[i] = (int)q[i]; g_lv[i] = (int)q[NLBL + i];
    } else {
        const int* q = (const int*)eli;
        g_lu[i] = q[i]; g_lv[i] = q[NLBL + i];
    }
}

// ---------------- CSR build: hierarchical scan -------------------------------
__global__ void scan1_k() {
    __shared__ int sh[256];
    int t = threadIdx.x;
    int i = blockIdx.x * 256 + t;
    int v = (i < NNODES) ? g_fill[i] : 0;
    sh[t] = v; __syncthreads();
    for (int o = 1; o < 256; o <<= 1) {
        int a = (t >= o) ? sh[t - o] : 0;
        __syncthreads();
        sh[t] += a;
        __syncthreads();
    }
    if (i < NNODES) g_incl[i] = sh[t];
    if (t == 255) g_bsum[blockIdx.x] = sh[255];
}

__global__ void scan2_k(int nb) {
    __shared__ int sh[256];
    int t = threadIdx.x;
    int v = (t < nb) ? g_bsum[t] : 0;
    sh[t] = v; __syncthreads();
    for (int o = 1; o < 256; o <<= 1) {
        int a = (t >= o) ? sh[t - o] : 0;
        __syncthreads();
        sh[t] += a;
        __syncthreads();
    }
    if (t < nb) g_bsum[t] = sh[t] - v;   // exclusive
}

__global__ void scan3_k() {
    int i = blockIdx.x * blockDim.x + threadIdx.x;
    if (i >= NNODES) return;
    int tot = g_bsum[i >> 8] + g_incl[i];
    int orig = g_fill[i];
    g_rowptr[i + 1] = tot;
    g_fill[i] = tot - orig;              // exclusive offsets for scatter
    if (i == 0) g_rowptr[0] = 0;
}

__global__ void scatter_k() {
    int i = blockIdx.x * blockDim.x + threadIdx.x;
    if (i >= ETOT) return;
    int pos = atomicAdd(&g_fill[g_edst[i]], 1);
    g_csr_src[pos] = g_esrc[i];
}

// ---------------- weight prep: transposes + fp16 conversion -----------------
__global__ void prep_weights_k(const float* __restrict__ W1,
                               const float* __restrict__ W2,
                               const float* __restrict__ Ws1) {
    int i = blockIdx.x * blockDim.x + threadIdx.x;
    if (i < 256 * 128) {
        int n = i >> 7, k = i & 127;
        g_Wt1h[i] = __float2half_rn(W1[k * 256 + n]);
    }
    int j = i - 256 * 128;
    if (j >= 0 && j < 256 * 256) {
        int n = j >> 8, k = j & 255;
        g_Wt2h[j] = __float2half_rn(W2[k * 256 + n]);
    }
    int l = i - 256 * 128 - 256 * 256;
    if (l >= 0 && l < 128 * 256) {
        int n = l >> 8, k = l & 255;
        g_Wtsh[l] = __float2half_rn((n < 64) ? Ws1[k * 64 + n]
                                             : Ws1[(256 + k) * 64 + (n - 64)]);
    }
}

// ---------------- convert x -> fp16 (8 floats per thread) -------------------
__global__ void conv_x_k(const float* __restrict__ x) {
    int i = blockIdx.x * blockDim.x + threadIdx.x;
    if (i >= NNODES * FIN / 8) return;
    const float4* xp = (const float4*)x;
    float4 a = xp[i * 2], b = xp[i * 2 + 1];
    uint4 u = { pack_h2(a.x, a.y), pack_h2(a.z, a.w),
                pack_h2(b.x, b.y), pack_h2(b.z, b.w) };
    ((uint4*)g_xh)[i] = u;
}

// ---------------- fp16 mma.sync GEMM (m16n8k16), fp16 gmem operands ---------
// C[M,NTR] = A[M,KDIM] @ Bt[NTR,KDIM]^T   (half gmem, fp32 accum)
// Block tile 128x64, 8 warps (4 in M x 2 in N), warp tile 32x32.
// LOGITS: fused head logits (64-col block == one head). OUTH: write half2 C.
template <int KDIM, int NTR, bool LOGITS, bool OUTH>
__global__ void __launch_bounds__(256) gemm_mma(
    const __half* __restrict__ A, const __half* __restrict__ Bt,
    void* __restrict__ Cv, int M,
    const float* __restrict__ a_src, const float* __restrict__ a_dst,
    float* __restrict__ als, float* __restrict__ ald)
{
    // smem in half2 units; pitch 20 -> fragment reads conflict-free
    __shared__ uint32_t As[128 * 20];
    __shared__ uint32_t Bs[64 * 20];
    __shared__ float red[4][128];

    int tid = threadIdx.x;
    int wid = tid >> 5, lane = tid & 31;
    int warp_m = wid & 3, warp_n = wid >> 2;
    int g = lane >> 2, t = lane & 3;

    int rowBase = blockIdx.y * 128;
    int colBase = blockIdx.x * 64;

    float c[2][4][4];
#pragma unroll
    for (int i = 0; i < 2; i++)
#pragma unroll
        for (int j = 0; j < 4; j++)
#pragma unroll
            for (int k = 0; k < 4; k++) c[i][j][k] = 0.f;

    constexpr int NC = KDIM / 32;
    const uint4 zero4 = {0u, 0u, 0u, 0u};
    uint4 ra[2], rb;
    int br = tid >> 2, bq = tid & 3;            // B slot (1 iter: 64 rows x 4)
    {
#pragma unroll
        for (int j = 0; j < 2; j++) {
            int slot = tid + 256 * j;
            int r = slot >> 2, q = slot & 3;
            int gr = rowBase + r;
            ra[j] = (gr < M) ? *(const uint4*)(A + (size_t)gr * KDIM + q * 8) : zero4;
        }
        rb = *(const uint4*)(Bt + (size_t)(colBase + br) * KDIM + bq * 8);
    }

    for (int kc = 0; kc < NC; kc++) {
        // store prefetched uint4s (8 halves) to smem
#pragma unroll
        for (int j = 0; j < 2; j++) {
            int slot = tid + 256 * j;
            int r = slot >> 2, q = slot & 3;
            *(uint4*)&As[r * 20 + q * 4] = ra[j];
        }
        *(uint4*)&Bs[br * 20 + bq * 4] = rb;
        __syncthreads();

        if (kc + 1 < NC) {
            int k0 = (kc + 1) * 32;
#pragma unroll
            for (int j = 0; j < 2; j++) {
                int slot = tid + 256 * j;
                int r = slot >> 2, q = slot & 3;
                int gr = rowBase + r;
                ra[j] = (gr < M) ? *(const uint4*)(A + (size_t)gr * KDIM + k0 + q * 8)
                                 : zero4;
            }
            rb = *(const uint4*)(Bt + (size_t)(colBase + br) * KDIM + k0 + bq * 8);
        }

        // two k16 steps per 32-half chunk
#pragma unroll
        for (int ks = 0; ks < 2; ks++) {
            int kk = ks * 8;   // half2 offset
            uint32_t a[2][4];
#pragma unroll
            for (int tm = 0; tm < 2; tm++) {
                int r0 = warp_m * 32 + tm * 16;
                a[tm][0] = As[(r0 + g) * 20 + kk + t];
                a[tm][1] = As[(r0 + g + 8) * 20 + kk + t];
                a[tm][2] = As[(r0 + g) * 20 + kk + t + 4];
                a[tm][3] = As[(r0 + g + 8) * 20 + kk + t + 4];
            }
            uint32_t b[4][2];
#pragma unroll
            for (int tn = 0; tn < 4; tn++) {
                int n0 = warp_n * 32 + tn * 8 + g;
                b[tn][0] = Bs[n0 * 20 + kk + t];
                b[tn][1] = Bs[n0 * 20 + kk + t + 4];
            }
#pragma unroll
            for (int tm = 0; tm < 2; tm++)
#pragma unroll
                for (int tn = 0; tn < 4; tn++)
                    mma16816(c[tm][tn][0], c[tm][tn][1], c[tm][tn][2], c[tm][tn][3],
                             a[tm][0], a[tm][1], a[tm][2], a[tm][3],
                             b[tn][0], b[tn][1]);
        }
        __syncthreads();
    }

    // epilogue: store C (+ fused logits)
    float ps[2][2], pd[2][2];
    if (LOGITS) {
#pragma unroll
        for (int tm = 0; tm < 2; tm++)
            ps[tm][0] = ps[tm][1] = pd[tm][0] = pd[tm][1] = 0.f;
    }
#pragma unroll
    for (int tm = 0; tm < 2; tm++) {
        int r0 = rowBase + warp_m * 32 + tm * 16 + g;
        int r1 = r0 + 8;
#pragma unroll
        for (int tn = 0; tn < 4; tn++) {
            int col = colBase + warp_n * 32 + tn * 8 + t * 2;
            if (LOGITS) {
                float s0 = a_src[col], s1 = a_src[col + 1];
                float d0 = a_dst[col], d1 = a_dst[col + 1];
                ps[tm][0] += c[tm][tn][0] * s0 + c[tm][tn][1] * s1;
                pd[tm][0] += c[tm][tn][0] * d0 + c[tm][tn][1] * d1;
                ps[tm][1] += c[tm][tn][2] * s0 + c[tm][tn][3] * s1;
                pd[tm][1] += c[tm][tn][2] * d0 + c[tm][tn][3] * d1;
            }
            if (OUTH) {
                __half* C = (__half*)Cv;
                if (r0 < M)
                    *(__half2*)(C + (size_t)r0 * NTR + col) =
                        __floats2half2_rn(c[tm][tn][0], c[tm][tn][1]);
                if (r1 < M)
                    *(__half2*)(C + (size_t)r1 * NTR + col) =
                        __floats2half2_rn(c[tm][tn][2], c[tm][tn][3]);
            } else {
                float* C = (float*)Cv;
                if (r0 < M)
                    *(float2*)(C + (size_t)r0 * NTR + col) = make_float2(c[tm][tn][0], c[tm][tn][1]);
                if (r1 < M)
                    *(float2*)(C + (size_t)r1 * NTR + col) = make_float2(c[tm][tn][2], c[tm][tn][3]);
            }
        }
    }
    if (LOGITS) {
#pragma unroll
        for (int tm = 0; tm < 2; tm++)
#pragma unroll
            for (int rr = 0; rr < 2; rr++) {
#pragma unroll
                for (int o = 1; o < 4; o <<= 1) {
                    ps[tm][rr] += __shfl_xor_sync(0xffffffffu, ps[tm][rr], o);
                    pd[tm][rr] += __shfl_xor_sync(0xffffffffu, pd[tm][rr], o);
                }
            }
        __syncthreads();
        if (t == 0) {
#pragma unroll
            for (int tm = 0; tm < 2; tm++) {
                int rl = warp_m * 32 + tm * 16 + g;
                red[warp_n * 2 + 0][rl]     = ps[tm][0];
                red[warp_n * 2 + 0][rl + 8] = ps[tm][1];
                red[warp_n * 2 + 1][rl]     = pd[tm][0];
                red[warp_n * 2 + 1][rl + 8] = pd[tm][1];
            }
        }
        __syncthreads();
        if (tid < 128) {
            int row = rowBase + tid;
            if (row < M) {
                int h = blockIdx.x;   // 64-col block == one head
                als[row * 4 + h] = red[0][tid] + red[2][tid];
                ald[row * 4 + h] = red[1][tid] + red[3][tid];
            }
        }
    }
}

// ---------------- fused softmax + aggregation + bias + ELU (fp16 out) -------
// warp per node; lane owns 8 channels, head hh = lane>>3.
__global__ void __launch_bounds__(256) aggregate_k(const float* __restrict__ bias) {
    int warp = threadIdx.x >> 5, lane = threadIdx.x & 31;
    int n = blockIdx.x * 8 + warp;
    if (n >= NNODES) return;
    int hh = lane >> 3;                         // 8 channels per lane -> head
    int beg = g_rowptr[n], end = g_rowptr[n + 1];
    const __half* hb = g_hbuf;
    float aldn = g_ald[n * 4 + hh];

    float acc[8] = {};
    float psum = 0.f;
#pragma unroll 2
    for (int k = beg; k < end; k++) {
        int s = g_csr_src[k];
        float e = g_als[s * 4 + hh] + aldn;
        float v = e > 0.f ? e : 0.2f * e;
        float w = __expf(v);
        psum += w;
        uint4 u = *(const uint4*)(hb + (size_t)s * 256 + lane * 8);
        const __half2* ph = (const __half2*)&u;
#pragma unroll
        for (int j = 0; j < 4; j++) {
            float2 f = __half22float2(ph[j]);
            acc[2 * j]     = fmaf(w, f.x, acc[2 * j]);
            acc[2 * j + 1] = fmaf(w, f.y, acc[2 * j + 1]);
        }
    }
    float inv = 1.f / psum;
    float4 b0 = *(const float4*)&bias[lane * 8];
    float4 b1 = *(const float4*)&bias[lane * 8 + 4];
    float o[8];
    o[0] = fmaf(acc[0], inv, b0.x); o[1] = fmaf(acc[1], inv, b0.y);
    o[2] = fmaf(acc[2], inv, b0.z); o[3] = fmaf(acc[3], inv, b0.w);
    o[4] = fmaf(acc[4], inv, b1.x); o[5] = fmaf(acc[5], inv, b1.y);
    o[6] = fmaf(acc[6], inv, b1.z); o[7] = fmaf(acc[7], inv, b1.w);
#pragma unroll
    for (int j = 0; j < 8; j++)
        o[j] = o[j] > 0.f ? o[j] : (__expf(o[j]) - 1.f);
    __half* zp = g_zh + (size_t)n * 256 + lane * 8;
    uint4 uo = { pack_h2(o[0], o[1]), pack_h2(o[2], o[3]),
                 pack_h2(o[4], o[5]), pack_h2(o[6], o[7]) };
    *(uint4*)zp = uo;
}

// ---------------- fused scorer: out = relu(P[u]+R[v]+bs1) . Ws2 + bs2 -------
__global__ void score_k(const float* __restrict__ bs1, const float* __restrict__ Ws2,
                        const float* __restrict__ bs2, float* __restrict__ out) {
    int e = (blockIdx.x * blockDim.x + threadIdx.x) >> 5;
    int lane = threadIdx.x & 31;
    if (e >= NLBL) return;
    int u = g_lu[e], v = g_lv[e];
    const float* pu = g_pr + (size_t)u * 128;
    const float* rv = g_pr + (size_t)v * 128 + 64;
    float s = 0.f;
#pragma unroll
    for (int j = 0; j < 2; j++) {
        int c = lane + j * 32;
        float h = pu[c] + rv[c] + bs1[c];
        h = fmaxf(h, 0.f);
        s = fmaf(h, Ws2[c], s);
    }
#pragma unroll
    for (int o = 16; o; o >>= 1) s += __shfl_xor_sync(0xffffffffu, s, o);
    if (!lane) out[e] = s + bs2[0];
}

// ---------------- launcher --------------------------------------------------
extern "C" void kernel_launch(void* const* d_in, const int* in_sizes, int n_in,
                              void* d_out, int out_size) {
    const float* x   = (const float*)d_in[0];
    const void*  ei  = d_in[1];
    const void*  eli = d_in[2];
    const float* W1  = (const float*)d_in[3];
    const float* as1 = (const float*)d_in[4];
    const float* ad1 = (const float*)d_in[5];
    const float* b1  = (const float*)d_in[6];
    const float* W2  = (const float*)d_in[7];
    const float* as2 = (const float*)d_in[8];
    const float* ad2 = (const float*)d_in[9];
    const float* b2  = (const float*)d_in[10];
    const float* Ws1 = (const float*)d_in[11];
    const float* bs1 = (const float*)d_in[12];
    const float* Ws2 = (const float*)d_in[13];
    const float* bs2 = (const float*)d_in[14];
    float* out = (float*)d_out;

    __half *xh, *hptr, *zh, *wt1h, *wt2h, *wtsh;
    float *prptr, *alsp, *aldp;
    cudaGetSymbolAddress((void**)&xh, g_xh);
    cudaGetSymbolAddress((void**)&hptr, g_hbuf);
    cudaGetSymbolAddress((void**)&zh, g_zh);
    cudaGetSymbolAddress((void**)&wt1h, g_Wt1h);
    cudaGetSymbolAddress((void**)&wt2h, g_Wt2h);
    cudaGetSymbolAddress((void**)&wtsh, g_Wtsh);
    cudaGetSymbolAddress((void**)&prptr, g_pr);
    cudaGetSymbolAddress((void**)&alsp, g_als);
    cudaGetSymbolAddress((void**)&aldp, g_ald);

    // side stream + fork/join events (created once, on the non-capture
    // correctness call; host-side only, no device memory involved)
    static cudaStream_t s2 = nullptr;
    static cudaEvent_t evFork = nullptr, evJoin = nullptr;
    if (!s2) {
        cudaStreamCreateWithFlags(&s2, cudaStreamNonBlocking);
        cudaEventCreateWithFlags(&evFork, cudaEventDisableTiming);
        cudaEventCreateWithFlags(&evJoin, cudaEventDisableTiming);
    }

    // fork: CSR build chain on s2, concurrent with weight/x prep + GEMM1
    cudaEventRecord(evFork, 0);
    cudaStreamWaitEvent(s2, evFork, 0);

    init_k<<<(NNODES + 255) / 256, 256, 0, s2>>>(ei, eli);
    build_edges<<<(ETOT + 255) / 256, 256, 0, s2>>>(ei);
    build_labels<<<(NLBL + 255) / 256, 256, 0, s2>>>(eli);
    int nb = (NNODES + 255) / 256;   // 196
    scan1_k<<<nb, 256, 0, s2>>>();
    scan2_k<<<1, 256, 0, s2>>>(nb);
    scan3_k<<<(NNODES + 255) / 256, 256, 0, s2>>>();
    scatter_k<<<(ETOT + 255) / 256, 256, 0, s2>>>();
    cudaEventRecord(evJoin, s2);

    // main stream: weight + x prep, then layer-1 GEMM (independent of CSR)
    int wtot = 256 * 128 + 256 * 256 + 128 * 256;
    prep_weights_k<<<(wtot + 255) / 256, 256>>>(W1, W2, Ws1);
    conv_x_k<<<(NNODES * FIN / 8 + 255) / 256, 256>>>(x);

    int mrows = (NNODES + 127) / 128;   // 391
    gemm_mma<128, 256, true, true><<<dim3(4, mrows), 256>>>(xh, wt1h, hptr, NNODES,
                                                            as1, ad1, alsp, aldp);

    // join: aggregation needs both CSR and logits
    cudaStreamWaitEvent(0, evJoin, 0);

    // ---- layer 1 edge pipeline (softmax fused into aggregation) ----
    aggregate_k<<<(NNODES + 7) / 8, 256>>>(b1);

    // ---- layer 2 ----
    gemm_mma<256, 256, true, true><<<dim3(4, mrows), 256>>>(zh, wt2h, hptr, NNODES,
                                                            as2, ad2, alsp, aldp);
    aggregate_k<<<(NNODES + 7) / 8, 256>>>(b2);

    // ---- scorer ----
    gemm_mma<256, 128, false, false><<<dim3(2, mrows), 256>>>(zh, wtsh, prptr, NNODES,
                                                              nullptr, nullptr, nullptr, nullptr);
    score_k<<<(NLBL + 7) / 8, 256>>>(bs1, Ws2, bs2, out);
}

// round 10
// speedup vs baseline: 1.4122x; 1.4122x over previous
#include <cuda_runtime.h>
#include <cuda_fp16.h>
#include <math.h>
#include <stdint.h>

#define NNODES 50000
#define NEDGES 800000
#define ETOT   (NEDGES + NNODES)
#define NLBL   100000
#define FIN    128
#define HH     4
#define CC     64
#define DD     256

// ---------------- scratch (device globals; no allocation allowed) ----------
__device__ int    g_flag64_e;
__device__ int    g_rowptr[NNODES + 1];
__device__ int    g_fill[NNODES];
__device__ int    g_incl[NNODES];
__device__ int    g_bsum[256];
__device__ int    g_csr_src[ETOT];
__device__ int    g_esrc[ETOT];
__device__ int    g_edst[ETOT];
__device__ int    g_lu[NLBL];
__device__ int    g_lv[NLBL];
__device__ __half g_hbuf[(size_t)NNODES * DD];  // GEMM output (fp16) / agg input
__device__ float  g_zbuf[(size_t)NNODES * DD];  // agg output / next GEMM input
__device__ float  g_als[NNODES * HH];
__device__ float  g_ald[NNODES * HH];
__device__ float  g_pr[(size_t)NNODES * 128];   // scorer P|R per node
__device__ float  g_Wt1[256 * 128];             // W1^T  [256][128]
__device__ float  g_Wt2[256 * 256];             // W2^T  [256][256]
__device__ float  g_Wts[128 * 256];             // [Ws1_top|Ws1_bot]^T [128][256]

// ============================ helpers =======================================
__device__ __forceinline__ uint32_t pack_h2(float a, float b) {
    __half2 h = __floats2half2_rn(a, b);
    return *(uint32_t*)&h;
}

__device__ __forceinline__ void mma16816(float& c0, float& c1, float& c2, float& c3,
                                         uint32_t a0, uint32_t a1, uint32_t a2, uint32_t a3,
                                         uint32_t b0, uint32_t b1) {
    asm volatile(
        "mma.sync.aligned.m16n8k16.row.col.f32.f16.f16.f32 "
        "{%0,%1,%2,%3}, {%4,%5,%6,%7}, {%8,%9}, {%0,%1,%2,%3};"
        : "+f"(c0), "+f"(c1), "+f"(c2), "+f"(c3)
        : "r"(a0), "r"(a1), "r"(a2), "r"(a3), "r"(b0), "r"(b1));
}

__device__ __forceinline__ int check_is_i64(const long long* q) {
    int ok = 1;
#pragma unroll
    for (int i = 0; i < 8; i++) {
        long long v = q[i];
        if (v < 0 || v >= NNODES) ok = 0;
    }
    return ok;
}

// ---------------- init: zero hist + label conversion + dtype flag -----------
__global__ void init_k(const void* ei, const void* eli) {
    int i = blockIdx.x * blockDim.x + threadIdx.x;
    if (i < NNODES) g_fill[i] = 0;
    if (i < NLBL) {
        // per-thread dtype check (8 cached loads) avoids cross-thread flag race
        if (check_is_i64((const long long*)eli)) {
            const long long* q = (const long long*)eli;
            g_lu[i] = (int)q[i]; g_lv[i] = (int)q[NLBL + i];
        } else {
            const int* q = (const int*)eli;
            g_lu[i] = q[i]; g_lv[i] = q[NLBL + i];
        }
    }
    if (i == 0) g_flag64_e = check_is_i64((const long long*)ei);
}

// ---------------- edge conversion + self loops + histogram ------------------
__global__ void build_edges(const void* ei) {
    int i = blockIdx.x * blockDim.x + threadIdx.x;
    if (i >= ETOT) return;
    int s, d;
    if (i < NEDGES) {
        if (g_flag64_e) {
            const long long* q = (const long long*)ei;
            s = (int)q[i]; d = (int)q[NEDGES + i];
        } else {
            const int* q = (const int*)ei;
            s = q[i]; d = q[NEDGES + i];
        }
    } else {
        s = i - NEDGES; d = s;   // self loop
    }
    g_esrc[i] = s; g_edst[i] = d;
    atomicAdd(&g_fill[d], 1);
}

// ---------------- CSR build: hierarchical scan -------------------------------
__global__ void scan1_k() {
    __shared__ int sh[256];
    int t = threadIdx.x;
    int i = blockIdx.x * 256 + t;
    int v = (i < NNODES) ? g_fill[i] : 0;
    sh[t] = v; __syncthreads();
    for (int o = 1; o < 256; o <<= 1) {
        int a = (t >= o) ? sh[t - o] : 0;
        __syncthreads();
        sh[t] += a;
        __syncthreads();
    }
    if (i < NNODES) g_incl[i] = sh[t];
    if (t == 255) g_bsum[blockIdx.x] = sh[255];
}

__global__ void scan2_k(int nb) {
    __shared__ int sh[256];
    int t = threadIdx.x;
    int v = (t < nb) ? g_bsum[t] : 0;
    sh[t] = v; __syncthreads();
    for (int o = 1; o < 256; o <<= 1) {
        int a = (t >= o) ? sh[t - o] : 0;
        __syncthreads();
        sh[t] += a;
        __syncthreads();
    }
    if (t < nb) g_bsum[t] = sh[t] - v;   // exclusive
}

__global__ void scan3_k() {
    int i = blockIdx.x * blockDim.x + threadIdx.x;
    if (i >= NNODES) return;
    int tot = g_bsum[i >> 8] + g_incl[i];
    int orig = g_fill[i];
    g_rowptr[i + 1] = tot;
    g_fill[i] = tot - orig;              // exclusive offsets for scatter
    if (i == 0) g_rowptr[0] = 0;
}

__global__ void scatter_k() {
    int i = blockIdx.x * blockDim.x + threadIdx.x;
    if (i >= ETOT) return;
    int pos = atomicAdd(&g_fill[g_edst[i]], 1);
    g_csr_src[pos] = g_esrc[i];
}

// ---------------- weight prep (all transposes in one kernel) ----------------
__global__ void prep_weights_k(const float* __restrict__ W1,
                               const float* __restrict__ W2,
                               const float* __restrict__ Ws1) {
    int i = blockIdx.x * blockDim.x + threadIdx.x;
    if (i < 256 * 128) {
        int n = i >> 7, k = i & 127;
        g_Wt1[i] = W1[k * 256 + n];
    }
    int j = i - 256 * 128;
    if (j >= 0 && j < 256 * 256) {
        int n = j >> 8, k = j & 255;
        g_Wt2[j] = W2[k * 256 + n];
    }
    int l = i - 256 * 128 - 256 * 256;
    if (l >= 0 && l < 128 * 256) {
        int n = l >> 8, k = l & 255;
        g_Wts[l] = (n < 64) ? Ws1[k * 64 + n] : Ws1[(256 + k) * 64 + (n - 64)];
    }
}

// ---------------- fp16 mma.sync GEMM (m16n8k16) with register prefetch ------
// C[M,NTR] = A[M,KDIM] @ Bt[NTR,KDIM]^T   (fp32 gmem, fp16 operands, fp32 acc)
// Block tile 128x64, 8 warps (4 in M x 2 in N), warp tile 32x32.
// LOGITS: fused head logits (64-col block == one head). OUTH: write half2 C.
template <int KDIM, int NTR, bool LOGITS, bool OUTH>
__global__ void __launch_bounds__(256) gemm_mma(
    const float* __restrict__ A, const float* __restrict__ Bt,
    void* __restrict__ Cv, int M,
    const float* __restrict__ a_src, const float* __restrict__ a_dst,
    float* __restrict__ als, float* __restrict__ ald)
{
    // smem in half2 units; pitch 20 -> fragment reads conflict-free
    __shared__ uint32_t As[128 * 20];
    __shared__ uint32_t Bs[64 * 20];
    __shared__ float red[4][128];

    int tid = threadIdx.x;
    int wid = tid >> 5, lane = tid & 31;
    int warp_m = wid & 3, warp_n = wid >> 2;
    int g = lane >> 2, t = lane & 3;

    int rowBase = blockIdx.y * 128;
    int colBase = blockIdx.x * 64;

    float c[2][4][4];
#pragma unroll
    for (int i = 0; i < 2; i++)
#pragma unroll
        for (int j = 0; j < 4; j++)
#pragma unroll
            for (int k = 0; k < 4; k++) c[i][j][k] = 0.f;

    constexpr int NC = KDIM / 32;
    float4 ra[4], rb[2];
    {
#pragma unroll
        for (int j = 0; j < 4; j++) {
            int idx = tid + 256 * j;
            int r = idx >> 3, q = idx & 7;
            int gr = rowBase + r;
            ra[j] = (gr < M) ? *(const float4*)(A + (size_t)gr * KDIM + q * 4)
                             : make_float4(0.f, 0.f, 0.f, 0.f);
        }
#pragma unroll
        for (int j = 0; j < 2; j++) {
            int idx = tid + 256 * j;
            int r = idx >> 3, q = idx & 7;
            rb[j] = *(const float4*)(Bt + (size_t)(colBase + r) * KDIM + q * 4);
        }
    }

    for (int kc = 0; kc < NC; kc++) {
        // store prefetched regs (converted to half2) to smem
#pragma unroll
        for (int j = 0; j < 4; j++) {
            int idx = tid + 256 * j;
            int r = idx >> 3, q = idx & 7;
            uint2 u = { pack_h2(ra[j].x, ra[j].y), pack_h2(ra[j].z, ra[j].w) };
            *(uint2*)&As[r * 20 + q * 2] = u;
        }
#pragma unroll
        for (int j = 0; j < 2; j++) {
            int idx = tid + 256 * j;
            int r = idx >> 3, q = idx & 7;
            uint2 u = { pack_h2(rb[j].x, rb[j].y), pack_h2(rb[j].z, rb[j].w) };
            *(uint2*)&Bs[r * 20 + q * 2] = u;
        }
        __syncthreads();

        if (kc + 1 < NC) {
            int k0 = (kc + 1) * 32;
#pragma unroll
            for (int j = 0; j < 4; j++) {
                int idx = tid + 256 * j;
                int r = idx >> 3, q = idx & 7;
                int gr = rowBase + r;
                ra[j] = (gr < M) ? *(const float4*)(A + (size_t)gr * KDIM + k0 + q * 4)
                                 : make_float4(0.f, 0.f, 0.f, 0.f);
            }
#pragma unroll
            for (int j = 0; j < 2; j++) {
                int idx = tid + 256 * j;
                int r = idx >> 3, q = idx & 7;
                rb[j] = *(const float4*)(Bt + (size_t)(colBase + r) * KDIM + k0 + q * 4);
            }
        }

        // two k16 steps per 32-float chunk
#pragma unroll
        for (int ks = 0; ks < 2; ks++) {
            int kk = ks * 8;   // half2 offset
            uint32_t a[2][4];
#pragma unroll
            for (int tm = 0; tm < 2; tm++) {
                int r0 = warp_m * 32 + tm * 16;
                a[tm][0] = As[(r0 + g) * 20 + kk + t];
                a[tm][1] = As[(r0 + g + 8) * 20 + kk + t];
                a[tm][2] = As[(r0 + g) * 20 + kk + t + 4];
                a[tm][3] = As[(r0 + g + 8) * 20 + kk + t + 4];
            }
            uint32_t b[4][2];
#pragma unroll
            for (int tn = 0; tn < 4; tn++) {
                int n0 = warp_n * 32 + tn * 8 + g;
                b[tn][0] = Bs[n0 * 20 + kk + t];
                b[tn][1] = Bs[n0 * 20 + kk + t + 4];
            }
#pragma unroll
            for (int tm = 0; tm < 2; tm++)
#pragma unroll
                for (int tn = 0; tn < 4; tn++)
                    mma16816(c[tm][tn][0], c[tm][tn][1], c[tm][tn][2], c[tm][tn][3],
                             a[tm][0], a[tm][1], a[tm][2], a[tm][3],
                             b[tn][0], b[tn][1]);
        }
        __syncthreads();
    }

    // epilogue: store C (+ fused logits)
    float ps[2][2], pd[2][2];
    if (LOGITS) {
#pragma unroll
        for (int tm = 0; tm < 2; tm++)
            ps[tm][0] = ps[tm][1] = pd[tm][0] = pd[tm][1] = 0.f;
    }
#pragma unroll
    for (int tm = 0; tm < 2; tm++) {
        int r0 = rowBase + warp_m * 32 + tm * 16 + g;
        int r1 = r0 + 8;
#pragma unroll
        for (int tn = 0; tn < 4; tn++) {
            int col = colBase + warp_n * 32 + tn * 8 + t * 2;
            if (LOGITS) {
                float s0 = a_src[col], s1 = a_src[col + 1];
                float d0 = a_dst[col], d1 = a_dst[col + 1];
                ps[tm][0] += c[tm][tn][0] * s0 + c[tm][tn][1] * s1;
                pd[tm][0] += c[tm][tn][0] * d0 + c[tm][tn][1] * d1;
                ps[tm][1] += c[tm][tn][2] * s0 + c[tm][tn][3] * s1;
                pd[tm][1] += c[tm][tn][2] * d0 + c[tm][tn][3] * d1;
            }
            if (OUTH) {
                __half* C = (__half*)Cv;
                if (r0 < M)
                    *(__half2*)(C + (size_t)r0 * NTR + col) =
                        __floats2half2_rn(c[tm][tn][0], c[tm][tn][1]);
                if (r1 < M)
                    *(__half2*)(C + (size_t)r1 * NTR + col) =
                        __floats2half2_rn(c[tm][tn][2], c[tm][tn][3]);
            } else {
                float* C = (float*)Cv;
                if (r0 < M)
                    *(float2*)(C + (size_t)r0 * NTR + col) = make_float2(c[tm][tn][0], c[tm][tn][1]);
                if (r1 < M)
                    *(float2*)(C + (size_t)r1 * NTR + col) = make_float2(c[tm][tn][2], c[tm][tn][3]);
            }
        }
    }
    if (LOGITS) {
#pragma unroll
        for (int tm = 0; tm < 2; tm++)
#pragma unroll
            for (int rr = 0; rr < 2; rr++) {
#pragma unroll
                for (int o = 1; o < 4; o <<= 1) {
                    ps[tm][rr] += __shfl_xor_sync(0xffffffffu, ps[tm][rr], o);
                    pd[tm][rr] += __shfl_xor_sync(0xffffffffu, pd[tm][rr], o);
                }
            }
        __syncthreads();
        if (t == 0) {
#pragma unroll
            for (int tm = 0; tm < 2; tm++) {
                int rl = warp_m * 32 + tm * 16 + g;
                red[warp_n * 2 + 0][rl]     = ps[tm][0];
                red[warp_n * 2 + 0][rl + 8] = ps[tm][1];
                red[warp_n * 2 + 1][rl]     = pd[tm][0];
                red[warp_n * 2 + 1][rl + 8] = pd[tm][1];
            }
        }
        __syncthreads();
        if (tid < 128) {
            int row = rowBase + tid;
            if (row < M) {
                int h = blockIdx.x;   // 64-col block == one head
                als[row * 4 + h] = red[0][tid] + red[2][tid];
                ald[row * 4 + h] = red[1][tid] + red[3][tid];
            }
        }
    }
}

// ---------------- fused softmax + aggregation + bias + ELU ------------------
// warp per node; lane owns 8 channels, head hh = lane>>3.
__global__ void __launch_bounds__(256) aggregate_k(const float* __restrict__ bias) {
    int warp = threadIdx.x >> 5, lane = threadIdx.x & 31;
    int n = blockIdx.x * 8 + warp;
    if (n >= NNODES) return;
    int hh = lane >> 3;                         // 8 channels per lane -> head
    int beg = g_rowptr[n], end = g_rowptr[n + 1];
    const __half* hb = g_hbuf;
    float aldn = g_ald[n * 4 + hh];

    float acc[8] = {};
    float psum = 0.f;
#pragma unroll 4
    for (int k = beg; k < end; k++) {
        int s = g_csr_src[k];
        float e = g_als[s * 4 + hh] + aldn;
        float v = e > 0.f ? e : 0.2f * e;
        float w = __expf(v);
        psum += w;
        uint4 u = *(const uint4*)(hb + (size_t)s * 256 + lane * 8);
        const __half2* ph = (const __half2*)&u;
#pragma unroll
        for (int j = 0; j < 4; j++) {
            float2 f = __half22float2(ph[j]);
            acc[2 * j]     = fmaf(w, f.x, acc[2 * j]);
            acc[2 * j + 1] = fmaf(w, f.y, acc[2 * j + 1]);
        }
    }
    float inv = 1.f / psum;
    float4 b0 = *(const float4*)&bias[lane * 8];
    float4 b1 = *(const float4*)&bias[lane * 8 + 4];
    float o[8];
    o[0] = fmaf(acc[0], inv, b0.x); o[1] = fmaf(acc[1], inv, b0.y);
    o[2] = fmaf(acc[2], inv, b0.z); o[3] = fmaf(acc[3], inv, b0.w);
    o[4] = fmaf(acc[4], inv, b1.x); o[5] = fmaf(acc[5], inv, b1.y);
    o[6] = fmaf(acc[6], inv, b1.z); o[7] = fmaf(acc[7], inv, b1.w);
#pragma unroll
    for (int j = 0; j < 8; j++)
        o[j] = o[j] > 0.f ? o[j] : (__expf(o[j]) - 1.f);
    float* zp = g_zbuf + (size_t)n * 256 + lane * 8;
    *(float4*)zp       = make_float4(o[0], o[1], o[2], o[3]);
    *(float4*)(zp + 4) = make_float4(o[4], o[5], o[6], o[7]);
}

// ---------------- fused scorer: out = relu(P[u]+R[v]+bs1) . Ws2 + bs2 -------
__global__ void score_k(const float* __restrict__ bs1, const float* __restrict__ Ws2,
                        const float* __restrict__ bs2, float* __restrict__ out) {
    int e = (blockIdx.x * blockDim.x + threadIdx.x) >> 5;
    int lane = threadIdx.x & 31;
    if (e >= NLBL) return;
    int u = g_lu[e], v = g_lv[e];
    const float* pu = g_pr + (size_t)u * 128;
    const float* rv = g_pr + (size_t)v * 128 + 64;
    float s = 0.f;
#pragma unroll
    for (int j = 0; j < 2; j++) {
        int c = lane + j * 32;
        float h = pu[c] + rv[c] + bs1[c];
        h = fmaxf(h, 0.f);
        s = fmaf(h, Ws2[c], s);
    }
#pragma unroll
    for (int o = 16; o; o >>= 1) s += __shfl_xor_sync(0xffffffffu, s, o);
    if (!lane) out[e] = s + bs2[0];
}

// ---------------- launcher --------------------------------------------------
extern "C" void kernel_launch(void* const* d_in, const int* in_sizes, int n_in,
                              void* d_out, int out_size) {
    const float* x   = (const float*)d_in[0];
    const void*  ei  = d_in[1];
    const void*  eli = d_in[2];
    const float* W1  = (const float*)d_in[3];
    const float* as1 = (const float*)d_in[4];
    const float* ad1 = (const float*)d_in[5];
    const float* b1  = (const float*)d_in[6];
    const float* W2  = (const float*)d_in[7];
    const float* as2 = (const float*)d_in[8];
    const float* ad2 = (const float*)d_in[9];
    const float* b2  = (const float*)d_in[10];
    const float* Ws1 = (const float*)d_in[11];
    const float* bs1 = (const float*)d_in[12];
    const float* Ws2 = (const float*)d_in[13];
    const float* bs2 = (const float*)d_in[14];
    float* out = (float*)d_out;

    void *hptr;
    float *zptr, *prptr, *wt1, *wt2, *wts, *alsp, *aldp;
    cudaGetSymbolAddress(&hptr, g_hbuf);
    cudaGetSymbolAddress((void**)&zptr, g_zbuf);
    cudaGetSymbolAddress((void**)&prptr, g_pr);
    cudaGetSymbolAddress((void**)&wt1, g_Wt1);
    cudaGetSymbolAddress((void**)&wt2, g_Wt2);
    cudaGetSymbolAddress((void**)&wts, g_Wts);
    cudaGetSymbolAddress((void**)&alsp, g_als);
    cudaGetSymbolAddress((void**)&aldp, g_ald);

    // side stream + fork/join events (created once, on the non-capture
    // correctness call; host-side only, no device memory involved)
    static cudaStream_t s2 = nullptr;
    static cudaEvent_t evFork = nullptr, evJoin = nullptr;
    if (!s2) {
        cudaStreamCreateWithFlags(&s2, cudaStreamNonBlocking);
        cudaEventCreateWithFlags(&evFork, cudaEventDisableTiming);
        cudaEventCreateWithFlags(&evJoin, cudaEventDisableTiming);
    }

    // fork: CSR build chain on s2, concurrent with weight prep + GEMM1.
    // Submission order puts gemm_mma at global launch index 5 so the ncu
    // capture (-s 5 -c 1) profiles the GEMM instead of a prep kernel.
    cudaEventRecord(evFork, 0);
    cudaStreamWaitEvent(s2, evFork, 0);

    int wtot = 256 * 128 + 256 * 256 + 128 * 256;
    int nb = (NNODES + 255) / 256;   // 196
    int mrows = (NNODES + 127) / 128;   // 391

    prep_weights_k<<<(wtot + 255) / 256, 256>>>(W1, W2, Ws1);            // #0 main
    init_k<<<(NLBL + 255) / 256, 256, 0, s2>>>(ei, eli);                 // #1 s2
    build_edges<<<(ETOT + 255) / 256, 256, 0, s2>>>(ei);                 // #2 s2
    scan1_k<<<nb, 256, 0, s2>>>();                                       // #3 s2
    scan2_k<<<1, 256, 0, s2>>>(nb);                                      // #4 s2
    gemm_mma<128, 256, true, true><<<dim3(4, mrows), 256>>>(             // #5 main
        x, wt1, hptr, NNODES, as1, ad1, alsp, aldp);
    scan3_k<<<(NNODES + 255) / 256, 256, 0, s2>>>();                     // #6 s2
    scatter_k<<<(ETOT + 255) / 256, 256, 0, s2>>>();                     // #7 s2
    cudaEventRecord(evJoin, s2);

    // join: aggregation needs both CSR and logits
    cudaStreamWaitEvent(0, evJoin, 0);

    // ---- layer 1 edge pipeline (softmax fused into aggregation) ----
    aggregate_k<<<(NNODES + 7) / 8, 256>>>(b1);

    // ---- layer 2 ----
    gemm_mma<256, 256, true, true><<<dim3(4, mrows), 256>>>(zptr, wt2, hptr, NNODES,
                                                            as2, ad2, alsp, aldp);
    aggregate_k<<<(NNODES + 7) / 8, 256>>>(b2);

    // ---- scorer ----
    gemm_mma<256, 128, false, false><<<dim3(2, mrows), 256>>>(zptr, wts, prptr, NNODES,
                                                              nullptr, nullptr, nullptr, nullptr);
    score_k<<<(NLBL + 7) / 8, 256>>>(bs1, Ws2, bs2, out);
}

// round 11
// speedup vs baseline: 1.4155x; 1.0023x over previous
#include <cuda_runtime.h>
#include <cuda_fp16.h>
#include <math.h>
#include <stdint.h>

#define NNODES 50000
#define NEDGES 800000
#define ETOT   (NEDGES + NNODES)
#define NLBL   100000
#define FIN    128
#define HH     4
#define CC     64
#define DD     256

// ---------------- scratch (device globals; no allocation allowed) ----------
__device__ int    g_flag64_e;
__device__ int    g_rowptr[NNODES + 1];
__device__ int    g_fill[NNODES];
__device__ int    g_incl[NNODES];
__device__ int    g_bsum[256];
__device__ int    g_csr_src[ETOT];
__device__ int    g_esrc[ETOT];
__device__ int    g_edst[ETOT];
__device__ int    g_lu[NLBL];
__device__ int    g_lv[NLBL];
__device__ __half g_hbuf[(size_t)NNODES * DD];  // GEMM output (fp16) / agg input
__device__ float  g_zbuf[(size_t)NNODES * DD];  // agg output / next GEMM input
__device__ float  g_als[NNODES * HH];
__device__ float  g_ald[NNODES * HH];
__device__ float  g_pr[(size_t)NNODES * 128];   // scorer P|R per node
__device__ float  g_Wt1[256 * 128];             // W1^T  [256][128]
__device__ float  g_Wt2[256 * 256];             // W2^T  [256][256]
__device__ float  g_Wts[128 * 256];             // [Ws1_top|Ws1_bot]^T [128][256]

// ============================ helpers =======================================
__device__ __forceinline__ uint32_t pack_h2(float a, float b) {
    __half2 h = __floats2half2_rn(a, b);
    return *(uint32_t*)&h;
}

__device__ __forceinline__ void mma16816(float& c0, float& c1, float& c2, float& c3,
                                         uint32_t a0, uint32_t a1, uint32_t a2, uint32_t a3,
                                         uint32_t b0, uint32_t b1) {
    asm volatile(
        "mma.sync.aligned.m16n8k16.row.col.f32.f16.f16.f32 "
        "{%0,%1,%2,%3}, {%4,%5,%6,%7}, {%8,%9}, {%0,%1,%2,%3};"
        : "+f"(c0), "+f"(c1), "+f"(c2), "+f"(c3)
        : "r"(a0), "r"(a1), "r"(a2), "r"(a3), "r"(b0), "r"(b1));
}

__device__ __forceinline__ int check_is_i64(const long long* q) {
    int ok = 1;
#pragma unroll
    for (int i = 0; i < 8; i++) {
        long long v = q[i];
        if (v < 0 || v >= NNODES) ok = 0;
    }
    return ok;
}

// ---------------- init: zero hist + label conversion + dtype flag -----------
__global__ void init_k(const void* ei, const void* eli) {
    int i = blockIdx.x * blockDim.x + threadIdx.x;
    if (i < NNODES) g_fill[i] = 0;
    if (i < NLBL) {
        if (check_is_i64((const long long*)eli)) {
            const long long* q = (const long long*)eli;
            g_lu[i] = (int)q[i]; g_lv[i] = (int)q[NLBL + i];
        } else {
            const int* q = (const int*)eli;
            g_lu[i] = q[i]; g_lv[i] = q[NLBL + i];
        }
    }
    if (i == 0) g_flag64_e = check_is_i64((const long long*)ei);
}

// ---------------- edge conversion + self loops + histogram ------------------
__global__ void build_edges(const void* ei) {
    int i = blockIdx.x * blockDim.x + threadIdx.x;
    if (i >= ETOT) return;
    int s, d;
    if (i < NEDGES) {
        if (g_flag64_e) {
            const long long* q = (const long long*)ei;
            s = (int)q[i]; d = (int)q[NEDGES + i];
        } else {
            const int* q = (const int*)ei;
            s = q[i]; d = q[NEDGES + i];
        }
    } else {
        s = i - NEDGES; d = s;   // self loop
    }
    g_esrc[i] = s; g_edst[i] = d;
    atomicAdd(&g_fill[d], 1);
}

// ---------------- CSR build: hierarchical scan -------------------------------
__global__ void scan1_k() {
    __shared__ int sh[256];
    int t = threadIdx.x;
    int i = blockIdx.x * 256 + t;
    int v = (i < NNODES) ? g_fill[i] : 0;
    sh[t] = v; __syncthreads();
    for (int o = 1; o < 256; o <<= 1) {
        int a = (t >= o) ? sh[t - o] : 0;
        __syncthreads();
        sh[t] += a;
        __syncthreads();
    }
    if (i < NNODES) g_incl[i] = sh[t];
    if (t == 255) g_bsum[blockIdx.x] = sh[255];
}

__global__ void scan2_k(int nb) {
    __shared__ int sh[256];
    int t = threadIdx.x;
    int v = (t < nb) ? g_bsum[t] : 0;
    sh[t] = v; __syncthreads();
    for (int o = 1; o < 256; o <<= 1) {
        int a = (t >= o) ? sh[t - o] : 0;
        __syncthreads();
        sh[t] += a;
        __syncthreads();
    }
    if (t < nb) g_bsum[t] = sh[t] - v;   // exclusive
}

__global__ void scan3_k() {
    int i = blockIdx.x * blockDim.x + threadIdx.x;
    if (i >= NNODES) return;
    int tot = g_bsum[i >> 8] + g_incl[i];
    int orig = g_fill[i];
    g_rowptr[i + 1] = tot;
    g_fill[i] = tot - orig;              // exclusive offsets for scatter
    if (i == 0) g_rowptr[0] = 0;
}

__global__ void scatter_k() {
    int i = blockIdx.x * blockDim.x + threadIdx.x;
    if (i >= ETOT) return;
    int pos = atomicAdd(&g_fill[g_edst[i]], 1);
    g_csr_src[pos] = g_esrc[i];
}

// ---------------- weight prep (all transposes in one kernel) ----------------
__global__ void prep_weights_k(const float* __restrict__ W1,
                               const float* __restrict__ W2,
                               const float* __restrict__ Ws1) {
    int i = blockIdx.x * blockDim.x + threadIdx.x;
    if (i < 256 * 128) {
        int n = i >> 7, k = i & 127;
        g_Wt1[i] = W1[k * 256 + n];
    }
    int j = i - 256 * 128;
    if (j >= 0 && j < 256 * 256) {
        int n = j >> 8, k = j & 255;
        g_Wt2[j] = W2[k * 256 + n];
    }
    int l = i - 256 * 128 - 256 * 256;
    if (l >= 0 && l < 128 * 256) {
        int n = l >> 8, k = l & 255;
        g_Wts[l] = (n < 64) ? Ws1[k * 64 + n] : Ws1[(256 + k) * 64 + (n - 64)];
    }
}

// ---------------- fp16 mma.sync GEMM (m16n8k16), 128x128 block tile ---------
// C[M,NTR] = A[M,KDIM] @ Bt[NTR,KDIM]^T   (fp32 gmem, fp16 operands, fp32 acc)
// 512 threads = 16 warps (4 in M x 4 in N); warp tile 32x32 (identical
// per-warp microkernel to the measured-good 245us version).
// LOGITS: warp_n 0/1 -> head blockIdx.x*2, warp_n 2/3 -> +1. OUTH: half2 C.
template <int KDIM, int NTR, bool LOGITS, bool OUTH>
__global__ void __launch_bounds__(512) gemm_mma(
    const float* __restrict__ A, const float* __restrict__ Bt,
    void* __restrict__ Cv, int M,
    const float* __restrict__ a_src, const float* __restrict__ a_dst,
    float* __restrict__ als, float* __restrict__ ald)
{
    // smem in half2 units; pitch 20 -> fragment reads conflict-free
    __shared__ uint32_t As[128 * 20];
    __shared__ uint32_t Bs[128 * 20];
    __shared__ float red[2][4][128];   // [src/dst][warp_n][row]

    int tid = threadIdx.x;
    int wid = tid >> 5, lane = tid & 31;
    int warp_m = wid & 3, warp_n = wid >> 2;     // 4 x 4 warps
    int g = lane >> 2, t = lane & 3;

    int rowBase = blockIdx.y * 128;
    int colBase = blockIdx.x * 128;

    float c[2][4][4];
#pragma unroll
    for (int i = 0; i < 2; i++)
#pragma unroll
        for (int j = 0; j < 4; j++)
#pragma unroll
            for (int k = 0; k < 4; k++) c[i][j][k] = 0.f;

    constexpr int NC = KDIM / 32;
    float4 ra[2], rb[2];
    {
#pragma unroll
        for (int j = 0; j < 2; j++) {
            int slot = tid + 512 * j;            // 0..1023
            int r = slot >> 3, q = slot & 7;
            int gr = rowBase + r;
            ra[j] = (gr < M) ? *(const float4*)(A + (size_t)gr * KDIM + q * 4)
                             : make_float4(0.f, 0.f, 0.f, 0.f);
            rb[j] = *(const float4*)(Bt + (size_t)(colBase + r) * KDIM + q * 4);
        }
    }

    for (int kc = 0; kc < NC; kc++) {
        // store prefetched regs (converted to half2) to smem
#pragma unroll
        for (int j = 0; j < 2; j++) {
            int slot = tid + 512 * j;
            int r = slot >> 3, q = slot & 7;
            uint2 ua = { pack_h2(ra[j].x, ra[j].y), pack_h2(ra[j].z, ra[j].w) };
            *(uint2*)&As[r * 20 + q * 2] = ua;
            uint2 ub = { pack_h2(rb[j].x, rb[j].y), pack_h2(rb[j].z, rb[j].w) };
            *(uint2*)&Bs[r * 20 + q * 2] = ub;
        }
        __syncthreads();

        if (kc + 1 < NC) {
            int k0 = (kc + 1) * 32;
#pragma unroll
            for (int j = 0; j < 2; j++) {
                int slot = tid + 512 * j;
                int r = slot >> 3, q = slot & 7;
                int gr = rowBase + r;
                ra[j] = (gr < M) ? *(const float4*)(A + (size_t)gr * KDIM + k0 + q * 4)
                                 : make_float4(0.f, 0.f, 0.f, 0.f);
                rb[j] = *(const float4*)(Bt + (size_t)(colBase + r) * KDIM + k0 + q * 4);
            }
        }

        // two k16 steps per 32-float chunk
#pragma unroll
        for (int ks = 0; ks < 2; ks++) {
            int kk = ks * 8;   // half2 offset
            uint32_t a[2][4];
#pragma unroll
            for (int tm = 0; tm < 2; tm++) {
                int r0 = warp_m * 32 + tm * 16;
                a[tm][0] = As[(r0 + g) * 20 + kk + t];
                a[tm][1] = As[(r0 + g + 8) * 20 + kk + t];
                a[tm][2] = As[(r0 + g) * 20 + kk + t + 4];
                a[tm][3] = As[(r0 + g + 8) * 20 + kk + t + 4];
            }
            uint32_t b[4][2];
#pragma unroll
            for (int tn = 0; tn < 4; tn++) {
                int n0 = warp_n * 32 + tn * 8 + g;
                b[tn][0] = Bs[n0 * 20 + kk + t];
                b[tn][1] = Bs[n0 * 20 + kk + t + 4];
            }
#pragma unroll
            for (int tm = 0; tm < 2; tm++)
#pragma unroll
                for (int tn = 0; tn < 4; tn++)
                    mma16816(c[tm][tn][0], c[tm][tn][1], c[tm][tn][2], c[tm][tn][3],
                             a[tm][0], a[tm][1], a[tm][2], a[tm][3],
                             b[tn][0], b[tn][1]);
        }
        __syncthreads();
    }

    // epilogue: store C (+ fused logits)
    float ps[2][2], pd[2][2];
    if (LOGITS) {
#pragma unroll
        for (int tm = 0; tm < 2; tm++)
            ps[tm][0] = ps[tm][1] = pd[tm][0] = pd[tm][1] = 0.f;
    }
#pragma unroll
    for (int tm = 0; tm < 2; tm++) {
        int r0 = rowBase + warp_m * 32 + tm * 16 + g;
        int r1 = r0 + 8;
#pragma unroll
        for (int tn = 0; tn < 4; tn++) {
            int col = colBase + warp_n * 32 + tn * 8 + t * 2;
            if (LOGITS) {
                float s0 = a_src[col], s1 = a_src[col + 1];
                float d0 = a_dst[col], d1 = a_dst[col + 1];
                ps[tm][0] += c[tm][tn][0] * s0 + c[tm][tn][1] * s1;
                pd[tm][0] += c[tm][tn][0] * d0 + c[tm][tn][1] * d1;
                ps[tm][1] += c[tm][tn][2] * s0 + c[tm][tn][3] * s1;
                pd[tm][1] += c[tm][tn][2] * d0 + c[tm][tn][3] * d1;
            }
            if (OUTH) {
                __half* C = (__half*)Cv;
                if (r0 < M)
                    *(__half2*)(C + (size_t)r0 * NTR + col) =
                        __floats2half2_rn(c[tm][tn][0], c[tm][tn][1]);
                if (r1 < M)
                    *(__half2*)(C + (size_t)r1 * NTR + col) =
                        __floats2half2_rn(c[tm][tn][2], c[tm][tn][3]);
            } else {
                float* C = (float*)Cv;
                if (r0 < M)
                    *(float2*)(C + (size_t)r0 * NTR + col) = make_float2(c[tm][tn][0], c[tm][tn][1]);
                if (r1 < M)
                    *(float2*)(C + (size_t)r1 * NTR + col) = make_float2(c[tm][tn][2], c[tm][tn][3]);
            }
        }
    }
    if (LOGITS) {
        // reduce over t (4 lanes with same g)
#pragma unroll
        for (int tm = 0; tm < 2; tm++)
#pragma unroll
            for (int rr = 0; rr < 2; rr++) {
#pragma unroll
                for (int o = 1; o < 4; o <<= 1) {
                    ps[tm][rr] += __shfl_xor_sync(0xffffffffu, ps[tm][rr], o);
                    pd[tm][rr] += __shfl_xor_sync(0xffffffffu, pd[tm][rr], o);
                }
            }
        __syncthreads();
        if (t == 0) {
#pragma unroll
            for (int tm = 0; tm < 2; tm++) {
                int rl = warp_m * 32 + tm * 16 + g;
                red[0][warp_n][rl]     = ps[tm][0];
                red[0][warp_n][rl + 8] = ps[tm][1];
                red[1][warp_n][rl]     = pd[tm][0];
                red[1][warp_n][rl + 8] = pd[tm][1];
            }
        }
        __syncthreads();
        if (tid < 128) {
            int row = rowBase + tid;
            if (row < M) {
                int h0 = blockIdx.x * 2;   // 128-col block == two heads
                als[row * 4 + h0]     = red[0][0][tid] + red[0][1][tid];
                als[row * 4 + h0 + 1] = red[0][2][tid] + red[0][3][tid];
                ald[row * 4 + h0]     = red[1][0][tid] + red[1][1][tid];
                ald[row * 4 + h0 + 1] = red[1][2][tid] + red[1][3][tid];
            }
        }
    }
}

// ---------------- fused softmax + aggregation + bias + ELU ------------------
// warp per node; lane owns 8 channels, head hh = lane>>3.
__global__ void __launch_bounds__(256) aggregate_k(const float* __restrict__ bias) {
    int warp = threadIdx.x >> 5, lane = threadIdx.x & 31;
    int n = blockIdx.x * 8 + warp;
    if (n >= NNODES) return;
    int hh = lane >> 3;                         // 8 channels per lane -> head
    int beg = g_rowptr[n], end = g_rowptr[n + 1];
    const __half* hb = g_hbuf;
    float aldn = g_ald[n * 4 + hh];

    float acc[8] = {};
    float psum = 0.f;
#pragma unroll 2
    for (int k = beg; k < end; k++) {
        int s = g_csr_src[k];
        float e = g_als[s * 4 + hh] + aldn;
        float v = e > 0.f ? e : 0.2f * e;
        float w = __expf(v);
        psum += w;
        uint4 u = *(const uint4*)(hb + (size_t)s * 256 + lane * 8);
        const __half2* ph = (const __half2*)&u;
#pragma unroll
        for (int j = 0; j < 4; j++) {
            float2 f = __half22float2(ph[j]);
            acc[2 * j]     = fmaf(w, f.x, acc[2 * j]);
            acc[2 * j + 1] = fmaf(w, f.y, acc[2 * j + 1]);
        }
    }
    float inv = 1.f / psum;
    float4 b0 = *(const float4*)&bias[lane * 8];
    float4 b1 = *(const float4*)&bias[lane * 8 + 4];
    float o[8];
    o[0] = fmaf(acc[0], inv, b0.x); o[1] = fmaf(acc[1], inv, b0.y);
    o[2] = fmaf(acc[2], inv, b0.z); o[3] = fmaf(acc[3], inv, b0.w);
    o[4] = fmaf(acc[4], inv, b1.x); o[5] = fmaf(acc[5], inv, b1.y);
    o[6] = fmaf(acc[6], inv, b1.z); o[7] = fmaf(acc[7], inv, b1.w);
#pragma unroll
    for (int j = 0; j < 8; j++)
        o[j] = o[j] > 0.f ? o[j] : (__expf(o[j]) - 1.f);
    float* zp = g_zbuf + (size_t)n * 256 + lane * 8;
    *(float4*)zp       = make_float4(o[0], o[1], o[2], o[3]);
    *(float4*)(zp + 4) = make_float4(o[4], o[5], o[6], o[7]);
}

// ---------------- fused scorer: out = relu(P[u]+R[v]+bs1) . Ws2 + bs2 -------
__global__ void score_k(const float* __restrict__ bs1, const float* __restrict__ Ws2,
                        const float* __restrict__ bs2, float* __restrict__ out) {
    int e = (blockIdx.x * blockDim.x + threadIdx.x) >> 5;
    int lane = threadIdx.x & 31;
    if (e >= NLBL) return;
    int u = g_lu[e], v = g_lv[e];
    const float* pu = g_pr + (size_t)u * 128;
    const float* rv = g_pr + (size_t)v * 128 + 64;
    float s = 0.f;
#pragma unroll
    for (int j = 0; j < 2; j++) {
        int c = lane + j * 32;
        float h = pu[c] + rv[c] + bs1[c];
        h = fmaxf(h, 0.f);
        s = fmaf(h, Ws2[c], s);
    }
#pragma unroll
    for (int o = 16; o; o >>= 1) s += __shfl_xor_sync(0xffffffffu, s, o);
    if (!lane) out[e] = s + bs2[0];
}

// ---------------- launcher --------------------------------------------------
extern "C" void kernel_launch(void* const* d_in, const int* in_sizes, int n_in,
                              void* d_out, int out_size) {
    const float* x   = (const float*)d_in[0];
    const void*  ei  = d_in[1];
    const void*  eli = d_in[2];
    const float* W1  = (const float*)d_in[3];
    const float* as1 = (const float*)d_in[4];
    const float* ad1 = (const float*)d_in[5];
    const float* b1  = (const float*)d_in[6];
    const float* W2  = (const float*)d_in[7];
    const float* as2 = (const float*)d_in[8];
    const float* ad2 = (const float*)d_in[9];
    const float* b2  = (const float*)d_in[10];
    const float* Ws1 = (const float*)d_in[11];
    const float* bs1 = (const float*)d_in[12];
    const float* Ws2 = (const float*)d_in[13];
    const float* bs2 = (const float*)d_in[14];
    float* out = (float*)d_out;

    void *hptr;
    float *zptr, *prptr, *wt1, *wt2, *wts, *alsp, *aldp;
    cudaGetSymbolAddress(&hptr, g_hbuf);
    cudaGetSymbolAddress((void**)&zptr, g_zbuf);
    cudaGetSymbolAddress((void**)&prptr, g_pr);
    cudaGetSymbolAddress((void**)&wt1, g_Wt1);
    cudaGetSymbolAddress((void**)&wt2, g_Wt2);
    cudaGetSymbolAddress((void**)&wts, g_Wts);
    cudaGetSymbolAddress((void**)&alsp, g_als);
    cudaGetSymbolAddress((void**)&aldp, g_ald);

    // side stream + fork/join events (created once, on the non-capture
    // correctness call; host-side only, no device memory involved)
    static cudaStream_t s2 = nullptr;
    static cudaEvent_t evFork = nullptr, evJoin = nullptr;
    if (!s2) {
        cudaStreamCreateWithFlags(&s2, cudaStreamNonBlocking);
        cudaEventCreateWithFlags(&evFork, cudaEventDisableTiming);
        cudaEventCreateWithFlags(&evJoin, cudaEventDisableTiming);
    }

    // fork: CSR build chain on s2, concurrent with weight prep + GEMM1
    cudaEventRecord(evFork, 0);
    cudaStreamWaitEvent(s2, evFork, 0);

    int wtot = 256 * 128 + 256 * 256 + 128 * 256;
    int nb = (NNODES + 255) / 256;      // 196
    int mrows = (NNODES + 127) / 128;   // 391

    init_k<<<(NLBL + 255) / 256, 256, 0, s2>>>(ei, eli);
    build_edges<<<(ETOT + 255) / 256, 256, 0, s2>>>(ei);
    scan1_k<<<nb, 256, 0, s2>>>();
    scan2_k<<<1, 256, 0, s2>>>(nb);
    scan3_k<<<(NNODES + 255) / 256, 256, 0, s2>>>();
    scatter_k<<<(ETOT + 255) / 256, 256, 0, s2>>>();
    cudaEventRecord(evJoin, s2);

    // main stream: weight prep + layer-1 GEMM (independent of CSR)
    prep_weights_k<<<(wtot + 255) / 256, 256>>>(W1, W2, Ws1);
    gemm_mma<128, 256, true, true><<<dim3(2, mrows), 512>>>(
        x, wt1, hptr, NNODES, as1, ad1, alsp, aldp);

    // join: aggregation needs both CSR and logits
    cudaStreamWaitEvent(0, evJoin, 0);

    // ---- layer 1 edge pipeline (softmax fused into aggregation) ----
    aggregate_k<<<(NNODES + 7) / 8, 256>>>(b1);

    // ---- layer 2 ----
    gemm_mma<256, 256, true, true><<<dim3(2, mrows), 512>>>(zptr, wt2, hptr, NNODES,
                                                            as2, ad2, alsp, aldp);
    aggregate_k<<<(NNODES + 7) / 8, 256>>>(b2);

    // ---- scorer ----
    gemm_mma<256, 128, false, false><<<dim3(1, mrows), 512>>>(zptr, wts, prptr, NNODES,
                                                              nullptr, nullptr, nullptr, nullptr);
    score_k<<<(NLBL + 7) / 8, 256>>>(bs1, Ws2, bs2, out);
}